// round 12
// baseline (speedup 1.0000x reference)
#include <cuda_runtime.h>
#include <cuda_bf16.h>
#include <cuda_fp16.h>
#include <math.h>
#include <stdint.h>

#define B_  2
#define T_  2048
#define C_  2048
#define H_  16
#define D_  128
#define M_  (B_*T_)      // 4096
#define N_QKV (3*C_)     // 6144

// ---------------------------------------------------------------------------
// Device scratch (allocation-free per harness rules)
// ---------------------------------------------------------------------------
__device__ __half g_qh[(size_t)B_*H_*T_*D_];
__device__ __half g_ql[(size_t)B_*H_*T_*D_];
__device__ __half g_k [(size_t)B_*H_*T_*D_];   // single fp16
__device__ __half g_vt[(size_t)B_*H_*D_*T_];   // single fp16, transposed [B,H,D,T]

__device__ __half g_hA[(size_t)M_*C_];     // GEMM A operand, fp16 hi
__device__ __half g_lA[(size_t)M_*C_];     // GEMM A operand, fp16 lo
__device__ __half g_B1[(size_t)N_QKV*C_];  // W_qkv^T, single fp16
__device__ __half g_B2[(size_t)C_*C_];     // W_out^T, single fp16

// ---------------------------------------------------------------------------
// PTX helpers
// ---------------------------------------------------------------------------
__device__ __forceinline__ void mma16816h(float* c, const uint32_t* a, const uint32_t* b) {
    asm volatile(
        "mma.sync.aligned.m16n8k16.row.col.f32.f16.f16.f32 "
        "{%0,%1,%2,%3}, {%4,%5,%6,%7}, {%8,%9}, {%0,%1,%2,%3};"
        : "+f"(c[0]), "+f"(c[1]), "+f"(c[2]), "+f"(c[3])
        : "r"(a[0]), "r"(a[1]), "r"(a[2]), "r"(a[3]), "r"(b[0]), "r"(b[1]));
}

__device__ __forceinline__ void ldsm4(uint32_t* r, uint32_t addr) {
    asm volatile("ldmatrix.sync.aligned.m8n8.x4.shared.b16 {%0,%1,%2,%3}, [%4];"
        : "=r"(r[0]), "=r"(r[1]), "=r"(r[2]), "=r"(r[3]) : "r"(addr));
}

__device__ __forceinline__ uint32_t smem_to_u32(const void* p) {
    uint32_t a;
    asm("{ .reg .u64 t; cvta.to.shared.u64 t, %1; cvt.u32.u64 %0, t; }" : "=r"(a) : "l"(p));
    return a;
}

__device__ __forceinline__ void cp16(uint32_t dst, const void* src) {
    asm volatile("cp.async.cg.shared.global [%0], [%1], 16;" :: "r"(dst), "l"(src));
}
#define CP_COMMIT() asm volatile("cp.async.commit_group;" ::: "memory")
#define CP_WAIT0()  asm volatile("cp.async.wait_group 0;" ::: "memory")
#define CP_WAIT1()  asm volatile("cp.async.wait_group 1;" ::: "memory")

// pack two fp32 -> fp16x2 (lo = first arg -> lower half)
__device__ __forceinline__ uint32_t packh(float lo, float hi) {
    uint32_t r;
    asm("cvt.rn.f16x2.f32 %0, %1, %2;" : "=r"(r) : "f"(hi), "f"(lo));
    return r;
}

// ---------------------------------------------------------------------------
// fp32 -> fp16 (hi, lo) split;  fp32 -> fp16 single transpose
// ---------------------------------------------------------------------------
__global__ void split_kernel(const float* __restrict__ src,
                             __half* __restrict__ hi,
                             __half* __restrict__ lo, int n4)
{
    int i = blockIdx.x * blockDim.x + threadIdx.x;
    if (i >= n4) return;
    float4 v = ((const float4*)src)[i];
    __half h0 = __float2half(v.x);
    __half h1 = __float2half(v.y);
    __half h2 = __float2half(v.z);
    __half h3 = __float2half(v.w);
    __half l0 = __float2half(v.x - __half2float(h0));
    __half l1 = __float2half(v.y - __half2float(h1));
    __half l2 = __float2half(v.z - __half2float(h2));
    __half l3 = __float2half(v.w - __half2float(h3));
    __half2* hp = (__half2*)hi;
    __half2* lp = (__half2*)lo;
    hp[i*2]   = __half2{h0, h1};
    hp[i*2+1] = __half2{h2, h3};
    lp[i*2]   = __half2{l0, l1};
    lp[i*2+1] = __half2{l2, l3};
}

// Transpose + convert: W [K=2048, N] -> fp16 [N, 2048]
__global__ void tsplit1_kernel(const float* __restrict__ W,
                               __half* __restrict__ hi, int N)
{
    __shared__ float t[32][33];
    int n0 = blockIdx.x * 32, k0 = blockIdx.y * 32;
    int tx = threadIdx.x, ty = threadIdx.y;
    #pragma unroll
    for (int i = 0; i < 4; i++)
        t[ty + i*8][tx] = W[(size_t)(k0 + ty + i*8) * N + n0 + tx];
    __syncthreads();
    #pragma unroll
    for (int i = 0; i < 4; i++) {
        int r = ty + i*8;
        hi[(size_t)(n0 + r) * 2048 + k0 + tx] = __float2half(t[tx][r]);
    }
}

// ---------------------------------------------------------------------------
// HMMA fp16 2-term GEMM: C = (Ah+Al) * B^T.  cp.async 3-stage pipeline,
// ldmatrix fragments, CTA 128x128, 8 warps (4m x 2n), K-chunk 32, 2 CTAs/SM.
// EPI=1: RoPE; q -> fp16 hi/lo, k -> single fp16, v -> single fp16 transposed.
// EPI=0: plain fp32 store.
// ---------------------------------------------------------------------------
#define ASTR 40                          // padded fp16 row stride
#define TILE_ELEMS (128 * ASTR)          // 5120 elems per matrix tile
#define TILE_B     (TILE_ELEMS * 2)      // 10240 bytes
#define STAGE_B    (3 * TILE_B)          // 30720 bytes per stage (Ah, Al, B)
#define NSTAGE     3
#define SMEM_GEMM  (NSTAGE * STAGE_B)    // 92160 bytes -> 2 CTAs/SM
#define NCH        64                    // 2048 / 32

template<int EPI>
__global__ void __launch_bounds__(256, 2) hmma_gemm(
    const __half* __restrict__ hiA, const __half* __restrict__ loA,
    const __half* __restrict__ Bw,
    float* __restrict__ Cout, int Ntot)
{
    extern __shared__ char smraw[];
    const uint32_t sb = smem_to_u32(smraw);

    const int tid = threadIdx.x;
    const int lane = tid & 31;
    const int wid = tid >> 5;
    const int warp_m = wid & 3;
    const int warp_n = wid >> 2;
    const int bn = blockIdx.x * 128;
    const int bm = blockIdx.y * 128;

    float acc[2][8][4];
    #pragma unroll
    for (int mt = 0; mt < 2; mt++)
        #pragma unroll
        for (int nt = 0; nt < 8; nt++)
            #pragma unroll
            for (int e = 0; e < 4; e++) acc[mt][nt][e] = 0.0f;

    const int lrow = tid >> 2;
    const int lc   = (tid & 3) * 8;
    auto load_stage = [&](int st, int k0) {
        uint32_t bo = sb + st * STAGE_B;
        #pragma unroll
        for (int i = 0; i < 2; i++) {
            int row = lrow + i * 64;
            uint32_t so = (uint32_t)(row * ASTR + lc) * 2;
            size_t ga = (size_t)(bm + row) * 2048 + k0 + lc;
            size_t gb = (size_t)(bn + row) * 2048 + k0 + lc;
            cp16(bo + 0*TILE_B + so, hiA + ga);
            cp16(bo + 1*TILE_B + so, loA + ga);
            cp16(bo + 2*TILE_B + so, Bw + gb);
        }
    };

    const int a_row = warp_m * 32 + (lane & 7) + ((lane >> 3) & 1) * 8;
    const int a_k8  = (lane >> 4) * 8;
    const int b_row = warp_n * 64 + (lane & 7) + (lane >> 4) * 8;
    const int b_k8  = ((lane >> 3) & 1) * 8;

    auto compute_stage = [&](int st) {
        uint32_t bo = sb + st * STAGE_B;
        #pragma unroll
        for (int ks = 0; ks < 32; ks += 16) {
            uint32_t ah[2][4], al[2][4], bh[4][4];
            #pragma unroll
            for (int mt = 0; mt < 2; mt++) {
                uint32_t ao = (uint32_t)((a_row + mt * 16) * ASTR + ks + a_k8) * 2;
                ldsm4(ah[mt], bo + 0*TILE_B + ao);
                ldsm4(al[mt], bo + 1*TILE_B + ao);
            }
            #pragma unroll
            for (int p = 0; p < 4; p++) {
                uint32_t bo2 = (uint32_t)((b_row + p * 16) * ASTR + ks + b_k8) * 2;
                ldsm4(bh[p], bo + 2*TILE_B + bo2);
            }
            #pragma unroll
            for (int mt = 0; mt < 2; mt++)
                #pragma unroll
                for (int p = 0; p < 4; p++) {
                    mma16816h(acc[mt][2*p+0], ah[mt], &bh[p][0]);
                    mma16816h(acc[mt][2*p+0], al[mt], &bh[p][0]);
                    mma16816h(acc[mt][2*p+1], ah[mt], &bh[p][2]);
                    mma16816h(acc[mt][2*p+1], al[mt], &bh[p][2]);
                }
        }
    };

    load_stage(0, 0);
    CP_COMMIT();
    load_stage(1, 32);
    CP_COMMIT();

    for (int c = 0; c < NCH; c++) {
        CP_WAIT1();
        __syncthreads();
        compute_stage(c % NSTAGE);
        if (c + 2 < NCH)
            load_stage((c + 2) % NSTAGE, (c + 2) * 32);
        CP_COMMIT();
    }

    // ---- Epilogue ----
    const int lr = lane >> 2;
    const int lk = (lane & 3) * 2;

    if (EPI == 1) {
        const int sub = bn >> 11;              // 0=q, 1=k, 2=v
        const int h   = (bn >> 7) & (H_ - 1);
        const float ROPE_K = 9.210340371976184f / (float)D_;
        float invf[8];
        #pragma unroll
        for (int nt = 0; nt < 8; nt++)
            invf[nt] = expf(-(float)(warp_n * 64 + nt * 8 + lk) * ROPE_K);
        #pragma unroll
        for (int mt = 0; mt < 2; mt++) {
            #pragma unroll
            for (int half = 0; half < 2; half++) {
                int m = bm + warp_m * 32 + mt * 16 + lr + half * 8;
                int bidx = m >> 11;
                int t    = m & (T_ - 1);
                size_t rowoff = ((size_t)(bidx * H_ + h) * T_ + t) * D_;
                #pragma unroll
                for (int nt = 0; nt < 8; nt++) {
                    int d = warp_n * 64 + nt * 8 + lk;
                    float v0 = acc[mt][nt][half * 2 + 0];
                    float v1 = acc[mt][nt][half * 2 + 1];
                    if (sub < 2) {
                        float sn, cs;
                        sincosf((float)t * invf[nt], &sn, &cs);
                        float o0 = v0 * cs - v1 * sn;
                        float o1 = v1 * cs + v0 * sn;
                        v0 = o0; v1 = o1;
                    }
                    if (sub == 0) {
                        __half h0 = __float2half(v0);
                        __half h1 = __float2half(v1);
                        __half l0 = __float2half(v0 - __half2float(h0));
                        __half l1 = __float2half(v1 - __half2float(h1));
                        *(__half2*)(g_qh + rowoff + d) = __half2{h0, h1};
                        *(__half2*)(g_ql + rowoff + d) = __half2{l0, l1};
                    } else if (sub == 1) {
                        *(__half2*)(g_k + rowoff + d) =
                            __half2{__float2half(v0), __float2half(v1)};
                    } else {
                        size_t vb = ((size_t)(bidx * H_ + h) * D_ + d) * T_ + t;
                        g_vt[vb]      = __float2half(v0);
                        g_vt[vb + T_] = __float2half(v1);
                    }
                }
            }
        }
    } else {
        #pragma unroll
        for (int mt = 0; mt < 2; mt++) {
            #pragma unroll
            for (int half = 0; half < 2; half++) {
                int m = bm + warp_m * 32 + mt * 16 + lr + half * 8;
                float* dst = Cout + (size_t)m * Ntot + bn + warp_n * 64 + lk;
                #pragma unroll
                for (int nt = 0; nt < 8; nt++)
                    *(float2*)(dst + nt * 8) =
                        make_float2(acc[mt][nt][half * 2 + 0], acc[mt][nt][half * 2 + 1]);
            }
        }
    }
}

// ---------------------------------------------------------------------------
// HMMA flash attention, fp16 2-term: S = (Qh+Ql)K^T, O = (Ph+Pl)V.
// CTA: 128 queries, 8 warps (16 rows each). Key blocks of 64, cp.async
// double-buffered. Output -> fp16 hi/lo (out-proj A operand).
// ---------------------------------------------------------------------------
#define SQ_H   0
#define SQ_L   34816
#define SBUF0  69632
#define KSTG   0
#define VSTG   17408
#define STG_SZ 35840
#define SMEM_ATTN (SBUF0 + 2 * STG_SZ)   // 141312 bytes

__global__ void __launch_bounds__(256, 1) attn_hmma(
    __half* __restrict__ outh, __half* __restrict__ outl)
{
    extern __shared__ char sm[];
    const uint32_t sb = smem_to_u32(sm);

    const int tid  = threadIdx.x;
    const int lane = tid & 31;
    const int w    = tid >> 5;
    const int lr   = lane >> 2;
    const int q    = lane & 3;
    const int qt   = 15 - blockIdx.x;          // longest tiles first
    const int bh   = blockIdx.y;
    const int b    = bh >> 4;
    const int h    = bh & (H_ - 1);

    const size_t bhT = (size_t)bh * T_;

    // ---- load Q tile (128 x 128, hi/lo fp16) via cp.async ----
    {
        const __half* qh = g_qh + (bhT + qt * 128) * D_;
        const __half* ql = g_ql + (bhT + qt * 128) * D_;
        #pragma unroll
        for (int i = 0; i < 8; i++) {
            int idx = tid + i * 256;
            int row = idx >> 4, c = idx & 15;
            cp16(sb + SQ_H + row * 272 + c * 16, qh + row * D_ + c * 8);
            cp16(sb + SQ_L + row * 272 + c * 16, ql + row * D_ + c * 8);
        }
    }

    auto loadKV = [&](int blk, int buf) {
        uint32_t bo = sb + SBUF0 + buf * STG_SZ;
        const __half* kp = g_k  + (bhT + blk * 64) * D_;
        const __half* vp = g_vt + (size_t)bh * D_ * T_ + blk * 64;
        #pragma unroll
        for (int i = 0; i < 4; i++) {
            int idx = tid + i * 256;
            int row = idx >> 4, c = idx & 15;            // K: 64 rows x 16 chunks
            cp16(bo + KSTG + row * 272 + c * 16, kp + row * D_ + c * 8);
            int vr = idx >> 3, vc = idx & 7;             // V: 128 rows x 8 chunks
            cp16(bo + VSTG + vr * 144 + vc * 16, vp + (size_t)vr * T_ + vc * 8);
        }
    };

    loadKV(0, 0);
    CP_COMMIT();
    CP_WAIT0();
    __syncthreads();

    const int nblk = 2 * qt + 2;
    const float scale = 0.08838834764831845f;   // 1/sqrt(128)

    float mr0 = -INFINITY, mr1 = -INFINITY, lw0 = 0.0f, lw1 = 0.0f;
    float O[16][4];
    #pragma unroll
    for (int n = 0; n < 16; n++)
        #pragma unroll
        for (int e = 0; e < 4; e++) O[n][e] = 0.0f;

    const int rbase = qt * 128 + 16 * w;        // global row of lr==0

    for (int blk = 0; blk < nblk; blk++) {
        const uint32_t bo = sb + SBUF0 + (blk & 1) * STG_SZ;
        if (blk + 1 < nblk) {
            loadKV(blk + 1, (blk & 1) ^ 1);
            CP_COMMIT();
        }

        // ---- S = (Qh+Ql) K^T (16x64 per warp) ----
        float s[8][4];
        #pragma unroll
        for (int n = 0; n < 8; n++)
            #pragma unroll
            for (int e = 0; e < 4; e++) s[n][e] = 0.0f;

        #pragma unroll
        for (int kt = 0; kt < 8; kt++) {
            uint32_t ah[4], al[4];
            uint32_t ab = SQ_H + (16 * w + lr) * 272 + kt * 32 + 4 * q;
            ah[0] = *(const uint32_t*)(sm + ab);
            ah[1] = *(const uint32_t*)(sm + ab + 8 * 272);
            ah[2] = *(const uint32_t*)(sm + ab + 16);
            ah[3] = *(const uint32_t*)(sm + ab + 8 * 272 + 16);
            uint32_t lb = ab + (SQ_L - SQ_H);
            al[0] = *(const uint32_t*)(sm + lb);
            al[1] = *(const uint32_t*)(sm + lb + 8 * 272);
            al[2] = *(const uint32_t*)(sm + lb + 16);
            al[3] = *(const uint32_t*)(sm + lb + 8 * 272 + 16);
            #pragma unroll
            for (int nt = 0; nt < 8; nt++) {
                uint32_t bbo = (bo - sb) + KSTG + (nt * 8 + lr) * 272 + kt * 32 + 4 * q;
                uint32_t bhf[2];
                bhf[0] = *(const uint32_t*)(sm + bbo);
                bhf[1] = *(const uint32_t*)(sm + bbo + 16);
                mma16816h(s[nt], ah, bhf);
                mma16816h(s[nt], al, bhf);
            }
        }

        // ---- scale + causal mask ----
        const bool need_mask = (blk * 64 + 63) > rbase;
        #pragma unroll
        for (int nt = 0; nt < 8; nt++) {
            #pragma unroll
            for (int e = 0; e < 4; e++) {
                float v = s[nt][e] * scale;
                if (need_mask) {
                    int ckey = blk * 64 + nt * 8 + 2 * q + (e & 1);
                    int r = rbase + lr + ((e >> 1) ? 8 : 0);
                    if (ckey > r) v = -1e30f;
                }
                s[nt][e] = v;
            }
        }

        // ---- online softmax (intra-quad shuffles) ----
        float mx0 = -1e30f, mx1 = -1e30f;
        #pragma unroll
        for (int nt = 0; nt < 8; nt++) {
            mx0 = fmaxf(mx0, fmaxf(s[nt][0], s[nt][1]));
            mx1 = fmaxf(mx1, fmaxf(s[nt][2], s[nt][3]));
        }
        mx0 = fmaxf(mx0, __shfl_xor_sync(0xffffffff, mx0, 1));
        mx0 = fmaxf(mx0, __shfl_xor_sync(0xffffffff, mx0, 2));
        mx1 = fmaxf(mx1, __shfl_xor_sync(0xffffffff, mx1, 1));
        mx1 = fmaxf(mx1, __shfl_xor_sync(0xffffffff, mx1, 2));
        float mn0 = fmaxf(mr0, mx0);
        float mn1 = fmaxf(mr1, mx1);
        float alpha0 = __expf(mr0 - mn0);
        float alpha1 = __expf(mr1 - mn1);

        float sum0 = 0.0f, sum1 = 0.0f;
        uint32_t aPh[4][4], aPl[4][4];
        #pragma unroll
        for (int nt = 0; nt < 8; nt++) {
            float p0 = __expf(s[nt][0] - mn0);
            float p1 = __expf(s[nt][1] - mn0);
            float p2 = __expf(s[nt][2] - mn1);
            float p3 = __expf(s[nt][3] - mn1);
            sum0 += p0 + p1;
            sum1 += p2 + p3;
            float h0 = __half2float(__float2half(p0));
            float h1 = __half2float(__float2half(p1));
            float h2 = __half2float(__float2half(p2));
            float h3 = __half2float(__float2half(p3));
            int kt2 = nt >> 1;
            int hi2 = (nt & 1) << 1;
            aPh[kt2][hi2 + 0] = packh(h0, h1);
            aPh[kt2][hi2 + 1] = packh(h2, h3);
            aPl[kt2][hi2 + 0] = packh(p0 - h0, p1 - h1);
            aPl[kt2][hi2 + 1] = packh(p2 - h2, p3 - h3);
        }
        sum0 += __shfl_xor_sync(0xffffffff, sum0, 1);
        sum0 += __shfl_xor_sync(0xffffffff, sum0, 2);
        sum1 += __shfl_xor_sync(0xffffffff, sum1, 1);
        sum1 += __shfl_xor_sync(0xffffffff, sum1, 2);
        lw0 = lw0 * alpha0 + sum0;
        lw1 = lw1 * alpha1 + sum1;
        mr0 = mn0;
        mr1 = mn1;

        // ---- O = O*alpha + (Ph+Pl) V ----
        #pragma unroll
        for (int n = 0; n < 16; n++) {
            O[n][0] *= alpha0; O[n][1] *= alpha0;
            O[n][2] *= alpha1; O[n][3] *= alpha1;
        }
        #pragma unroll
        for (int kt2 = 0; kt2 < 4; kt2++) {
            #pragma unroll
            for (int nt2 = 0; nt2 < 16; nt2++) {
                uint32_t vbo = (bo - sb) + VSTG + (nt2 * 8 + lr) * 144 + kt2 * 32 + 4 * q;
                uint32_t bhf[2];
                bhf[0] = *(const uint32_t*)(sm + vbo);
                bhf[1] = *(const uint32_t*)(sm + vbo + 16);
                mma16816h(O[nt2], aPh[kt2], bhf);
                mma16816h(O[nt2], aPl[kt2], bhf);
            }
        }

        if (blk + 1 < nblk) {
            CP_WAIT0();
            __syncthreads();
        }
    }

    // ---- epilogue: normalize, split to fp16 hi/lo for the out-proj ----
    const float inv0 = 1.0f / lw0;
    const float inv1 = 1.0f / lw1;
    const int m0 = b * T_ + rbase + lr;
    const int m1 = m0 + 8;
    #pragma unroll
    for (int nt2 = 0; nt2 < 16; nt2++) {
        int col = h * D_ + nt2 * 8 + 2 * q;
        float o0 = O[nt2][0] * inv0, o1 = O[nt2][1] * inv0;
        float o2 = O[nt2][2] * inv1, o3 = O[nt2][3] * inv1;
        __half h0 = __float2half(o0), h1 = __float2half(o1);
        __half h2 = __float2half(o2), h3 = __float2half(o3);
        __half l0 = __float2half(o0 - __half2float(h0));
        __half l1 = __float2half(o1 - __half2float(h1));
        __half l2 = __float2half(o2 - __half2float(h2));
        __half l3 = __float2half(o3 - __half2float(h3));
        *(__half2*)(outh + (size_t)m0 * C_ + col) = __half2{h0, h1};
        *(__half2*)(outl + (size_t)m0 * C_ + col) = __half2{l0, l1};
        *(__half2*)(outh + (size_t)m1 * C_ + col) = __half2{h2, h3};
        *(__half2*)(outl + (size_t)m1 * C_ + col) = __half2{l2, l3};
    }
}

// ---------------------------------------------------------------------------
extern "C" void kernel_launch(void* const* d_in, const int* in_sizes, int n_in,
                              void* d_out, int out_size)
{
    const float* x     = (const float*)d_in[0];
    const float* W_qkv = (const float*)d_in[1];
    const float* W_out = (const float*)d_in[2];
    float* out = (float*)d_out;

    cudaFuncSetAttribute(attn_hmma,
                         cudaFuncAttributeMaxDynamicSharedMemorySize, SMEM_ATTN);
    cudaFuncSetAttribute(hmma_gemm<1>,
                         cudaFuncAttributeMaxDynamicSharedMemorySize, SMEM_GEMM);
    cudaFuncSetAttribute(hmma_gemm<0>,
                         cudaFuncAttributeMaxDynamicSharedMemorySize, SMEM_GEMM);

    __half *hA, *lA, *B1, *B2;
    cudaGetSymbolAddress((void**)&hA, g_hA);
    cudaGetSymbolAddress((void**)&lA, g_lA);
    cudaGetSymbolAddress((void**)&B1, g_B1);
    cudaGetSymbolAddress((void**)&B2, g_B2);

    const int n4 = (M_ * C_) / 4;

    // 1) split x -> fp16 hi/lo (A operand of QKV GEMM)
    split_kernel<<<(n4 + 255) / 256, 256>>>(x, hA, lA, n4);
    // 2) transpose+convert weights to single fp16
    tsplit1_kernel<<<dim3(N_QKV / 32, C_ / 32), dim3(32, 8)>>>(W_qkv, B1, N_QKV);
    tsplit1_kernel<<<dim3(C_ / 32, C_ / 32), dim3(32, 8)>>>(W_out, B2, C_);
    // 3) QKV projection + RoPE -> q fp16 hi/lo, k fp16, v fp16 transposed
    hmma_gemm<1><<<dim3(N_QKV / 128, M_ / 128), 256, SMEM_GEMM>>>(
        hA, lA, B1, nullptr, N_QKV);
    // 4) HMMA flash attention -> fp16 hi/lo (A operand of out-proj)
    attn_hmma<<<dim3(T_ / 128, B_ * H_), 256, SMEM_ATTN>>>(hA, lA);
    // 5) output projection -> d_out
    hmma_gemm<0><<<dim3(C_ / 128, M_ / 128), 256, SMEM_GEMM>>>(
        hA, lA, B2, out, C_);
}

// round 13
// speedup vs baseline: 1.0135x; 1.0135x over previous
#include <cuda_runtime.h>
#include <cuda_bf16.h>
#include <cuda_fp16.h>
#include <math.h>
#include <stdint.h>

#define B_  2
#define T_  2048
#define C_  2048
#define H_  16
#define D_  128
#define M_  (B_*T_)      // 4096
#define N_QKV (3*C_)     // 6144

// ---------------------------------------------------------------------------
// Device scratch (allocation-free per harness rules)
// ---------------------------------------------------------------------------
__device__ __half g_qh[(size_t)B_*H_*T_*D_];
__device__ __half g_ql[(size_t)B_*H_*T_*D_];
__device__ __half g_k [(size_t)B_*H_*T_*D_];   // single fp16
__device__ __half g_vt[(size_t)B_*H_*D_*T_];   // single fp16, transposed [B,H,D,T]

__device__ __half g_hA[(size_t)M_*C_];     // GEMM A operand, fp16 hi
__device__ __half g_lA[(size_t)M_*C_];     // GEMM A operand, fp16 lo
__device__ __half g_B1[(size_t)N_QKV*C_];  // W_qkv^T, single fp16
__device__ __half g_B2[(size_t)C_*C_];     // W_out^T, single fp16

// ---------------------------------------------------------------------------
// PTX helpers
// ---------------------------------------------------------------------------
__device__ __forceinline__ void mma16816h(float* c, const uint32_t* a, const uint32_t* b) {
    asm volatile(
        "mma.sync.aligned.m16n8k16.row.col.f32.f16.f16.f32 "
        "{%0,%1,%2,%3}, {%4,%5,%6,%7}, {%8,%9}, {%0,%1,%2,%3};"
        : "+f"(c[0]), "+f"(c[1]), "+f"(c[2]), "+f"(c[3])
        : "r"(a[0]), "r"(a[1]), "r"(a[2]), "r"(a[3]), "r"(b[0]), "r"(b[1]));
}

__device__ __forceinline__ void ldsm4(uint32_t* r, uint32_t addr) {
    asm volatile("ldmatrix.sync.aligned.m8n8.x4.shared.b16 {%0,%1,%2,%3}, [%4];"
        : "=r"(r[0]), "=r"(r[1]), "=r"(r[2]), "=r"(r[3]) : "r"(addr));
}

__device__ __forceinline__ uint32_t smem_to_u32(const void* p) {
    uint32_t a;
    asm("{ .reg .u64 t; cvta.to.shared.u64 t, %1; cvt.u32.u64 %0, t; }" : "=r"(a) : "l"(p));
    return a;
}

__device__ __forceinline__ void cp16(uint32_t dst, const void* src) {
    asm volatile("cp.async.cg.shared.global [%0], [%1], 16;" :: "r"(dst), "l"(src));
}
#define CP_COMMIT() asm volatile("cp.async.commit_group;" ::: "memory")
#define CP_WAIT0()  asm volatile("cp.async.wait_group 0;" ::: "memory")
#define CP_WAIT1()  asm volatile("cp.async.wait_group 1;" ::: "memory")

// pack two fp32 -> fp16x2 (lo = first arg -> lower half)
__device__ __forceinline__ uint32_t packh(float lo, float hi) {
    uint32_t r;
    asm("cvt.rn.f16x2.f32 %0, %1, %2;" : "=r"(r) : "f"(hi), "f"(lo));
    return r;
}

// ---------------------------------------------------------------------------
// fp32 -> fp16 (hi, lo) split;  fp32 -> fp16 single transpose
// ---------------------------------------------------------------------------
__global__ void split_kernel(const float* __restrict__ src,
                             __half* __restrict__ hi,
                             __half* __restrict__ lo, int n4)
{
    int i = blockIdx.x * blockDim.x + threadIdx.x;
    if (i >= n4) return;
    float4 v = ((const float4*)src)[i];
    __half h0 = __float2half(v.x);
    __half h1 = __float2half(v.y);
    __half h2 = __float2half(v.z);
    __half h3 = __float2half(v.w);
    __half l0 = __float2half(v.x - __half2float(h0));
    __half l1 = __float2half(v.y - __half2float(h1));
    __half l2 = __float2half(v.z - __half2float(h2));
    __half l3 = __float2half(v.w - __half2float(h3));
    __half2* hp = (__half2*)hi;
    __half2* lp = (__half2*)lo;
    hp[i*2]   = __half2{h0, h1};
    hp[i*2+1] = __half2{h2, h3};
    lp[i*2]   = __half2{l0, l1};
    lp[i*2+1] = __half2{l2, l3};
}

// Transpose + convert: W [K=2048, N] -> fp16 [N, 2048]
__global__ void tsplit1_kernel(const float* __restrict__ W,
                               __half* __restrict__ hi, int N)
{
    __shared__ float t[32][33];
    int n0 = blockIdx.x * 32, k0 = blockIdx.y * 32;
    int tx = threadIdx.x, ty = threadIdx.y;
    #pragma unroll
    for (int i = 0; i < 4; i++)
        t[ty + i*8][tx] = W[(size_t)(k0 + ty + i*8) * N + n0 + tx];
    __syncthreads();
    #pragma unroll
    for (int i = 0; i < 4; i++) {
        int r = ty + i*8;
        hi[(size_t)(n0 + r) * 2048 + k0 + tx] = __float2half(t[tx][r]);
    }
}

// ---------------------------------------------------------------------------
// HMMA fp16 2-term GEMM: C = (Ah+Al) * B^T.  cp.async 3-stage pipeline,
// ldmatrix fragments, CTA 128x128, 8 warps (4m x 2n), K-chunk 32, 2 CTAs/SM.
// EPI=1: RoPE; q -> fp16 hi/lo, k -> single fp16, v -> single fp16 transposed.
// EPI=0: plain fp32 store.   (UNCHANGED from R11/R12 — clock-noise control.)
// ---------------------------------------------------------------------------
#define ASTR 40                          // padded fp16 row stride
#define TILE_ELEMS (128 * ASTR)          // 5120 elems per matrix tile
#define TILE_B     (TILE_ELEMS * 2)      // 10240 bytes
#define STAGE_B    (3 * TILE_B)          // 30720 bytes per stage (Ah, Al, B)
#define NSTAGE     3
#define SMEM_GEMM  (NSTAGE * STAGE_B)    // 92160 bytes -> 2 CTAs/SM
#define NCH        64                    // 2048 / 32

template<int EPI>
__global__ void __launch_bounds__(256, 2) hmma_gemm(
    const __half* __restrict__ hiA, const __half* __restrict__ loA,
    const __half* __restrict__ Bw,
    float* __restrict__ Cout, int Ntot)
{
    extern __shared__ char smraw[];
    const uint32_t sb = smem_to_u32(smraw);

    const int tid = threadIdx.x;
    const int lane = tid & 31;
    const int wid = tid >> 5;
    const int warp_m = wid & 3;
    const int warp_n = wid >> 2;
    const int bn = blockIdx.x * 128;
    const int bm = blockIdx.y * 128;

    float acc[2][8][4];
    #pragma unroll
    for (int mt = 0; mt < 2; mt++)
        #pragma unroll
        for (int nt = 0; nt < 8; nt++)
            #pragma unroll
            for (int e = 0; e < 4; e++) acc[mt][nt][e] = 0.0f;

    const int lrow = tid >> 2;
    const int lc   = (tid & 3) * 8;
    auto load_stage = [&](int st, int k0) {
        uint32_t bo = sb + st * STAGE_B;
        #pragma unroll
        for (int i = 0; i < 2; i++) {
            int row = lrow + i * 64;
            uint32_t so = (uint32_t)(row * ASTR + lc) * 2;
            size_t ga = (size_t)(bm + row) * 2048 + k0 + lc;
            size_t gb = (size_t)(bn + row) * 2048 + k0 + lc;
            cp16(bo + 0*TILE_B + so, hiA + ga);
            cp16(bo + 1*TILE_B + so, loA + ga);
            cp16(bo + 2*TILE_B + so, Bw + gb);
        }
    };

    const int a_row = warp_m * 32 + (lane & 7) + ((lane >> 3) & 1) * 8;
    const int a_k8  = (lane >> 4) * 8;
    const int b_row = warp_n * 64 + (lane & 7) + (lane >> 4) * 8;
    const int b_k8  = ((lane >> 3) & 1) * 8;

    auto compute_stage = [&](int st) {
        uint32_t bo = sb + st * STAGE_B;
        #pragma unroll
        for (int ks = 0; ks < 32; ks += 16) {
            uint32_t ah[2][4], al[2][4], bh[4][4];
            #pragma unroll
            for (int mt = 0; mt < 2; mt++) {
                uint32_t ao = (uint32_t)((a_row + mt * 16) * ASTR + ks + a_k8) * 2;
                ldsm4(ah[mt], bo + 0*TILE_B + ao);
                ldsm4(al[mt], bo + 1*TILE_B + ao);
            }
            #pragma unroll
            for (int p = 0; p < 4; p++) {
                uint32_t bo2 = (uint32_t)((b_row + p * 16) * ASTR + ks + b_k8) * 2;
                ldsm4(bh[p], bo + 2*TILE_B + bo2);
            }
            #pragma unroll
            for (int mt = 0; mt < 2; mt++)
                #pragma unroll
                for (int p = 0; p < 4; p++) {
                    mma16816h(acc[mt][2*p+0], ah[mt], &bh[p][0]);
                    mma16816h(acc[mt][2*p+0], al[mt], &bh[p][0]);
                    mma16816h(acc[mt][2*p+1], ah[mt], &bh[p][2]);
                    mma16816h(acc[mt][2*p+1], al[mt], &bh[p][2]);
                }
        }
    };

    load_stage(0, 0);
    CP_COMMIT();
    load_stage(1, 32);
    CP_COMMIT();

    for (int c = 0; c < NCH; c++) {
        CP_WAIT1();
        __syncthreads();
        compute_stage(c % NSTAGE);
        if (c + 2 < NCH)
            load_stage((c + 2) % NSTAGE, (c + 2) * 32);
        CP_COMMIT();
    }

    // ---- Epilogue ----
    const int lr = lane >> 2;
    const int lk = (lane & 3) * 2;

    if (EPI == 1) {
        const int sub = bn >> 11;              // 0=q, 1=k, 2=v
        const int h   = (bn >> 7) & (H_ - 1);
        const float ROPE_K = 9.210340371976184f / (float)D_;
        float invf[8];
        #pragma unroll
        for (int nt = 0; nt < 8; nt++)
            invf[nt] = expf(-(float)(warp_n * 64 + nt * 8 + lk) * ROPE_K);
        #pragma unroll
        for (int mt = 0; mt < 2; mt++) {
            #pragma unroll
            for (int half = 0; half < 2; half++) {
                int m = bm + warp_m * 32 + mt * 16 + lr + half * 8;
                int bidx = m >> 11;
                int t    = m & (T_ - 1);
                size_t rowoff = ((size_t)(bidx * H_ + h) * T_ + t) * D_;
                #pragma unroll
                for (int nt = 0; nt < 8; nt++) {
                    int d = warp_n * 64 + nt * 8 + lk;
                    float v0 = acc[mt][nt][half * 2 + 0];
                    float v1 = acc[mt][nt][half * 2 + 1];
                    if (sub < 2) {
                        float sn, cs;
                        sincosf((float)t * invf[nt], &sn, &cs);
                        float o0 = v0 * cs - v1 * sn;
                        float o1 = v1 * cs + v0 * sn;
                        v0 = o0; v1 = o1;
                    }
                    if (sub == 0) {
                        __half h0 = __float2half(v0);
                        __half h1 = __float2half(v1);
                        __half l0 = __float2half(v0 - __half2float(h0));
                        __half l1 = __float2half(v1 - __half2float(h1));
                        *(__half2*)(g_qh + rowoff + d) = __half2{h0, h1};
                        *(__half2*)(g_ql + rowoff + d) = __half2{l0, l1};
                    } else if (sub == 1) {
                        *(__half2*)(g_k + rowoff + d) =
                            __half2{__float2half(v0), __float2half(v1)};
                    } else {
                        size_t vb = ((size_t)(bidx * H_ + h) * D_ + d) * T_ + t;
                        g_vt[vb]      = __float2half(v0);
                        g_vt[vb + T_] = __float2half(v1);
                    }
                }
            }
        }
    } else {
        #pragma unroll
        for (int mt = 0; mt < 2; mt++) {
            #pragma unroll
            for (int half = 0; half < 2; half++) {
                int m = bm + warp_m * 32 + mt * 16 + lr + half * 8;
                float* dst = Cout + (size_t)m * Ntot + bn + warp_n * 64 + lk;
                #pragma unroll
                for (int nt = 0; nt < 8; nt++)
                    *(float2*)(dst + nt * 8) =
                        make_float2(acc[mt][nt][half * 2 + 0], acc[mt][nt][half * 2 + 1]);
            }
        }
    }
}

// ---------------------------------------------------------------------------
// HMMA flash attention, fp16 2-term, ldmatrix fragments.
// CTA: 128 queries, 8 warps (16 rows each). Key blocks of 64, cp.async
// double-buffered. Output -> fp16 hi/lo (out-proj A operand).
// ---------------------------------------------------------------------------
#define SQ_H   0
#define SQ_L   34816
#define SBUF0  69632
#define KSTG   0
#define VSTG   17408
#define STG_SZ 35840
#define SMEM_ATTN (SBUF0 + 2 * STG_SZ)   // 141312 bytes

__global__ void __launch_bounds__(256, 1) attn_hmma(
    __half* __restrict__ outh, __half* __restrict__ outl)
{
    extern __shared__ char sm[];
    const uint32_t sb = smem_to_u32(sm);

    const int tid  = threadIdx.x;
    const int lane = tid & 31;
    const int w    = tid >> 5;
    const int lr   = lane >> 2;
    const int q    = lane & 3;
    const int qt   = 15 - blockIdx.x;          // longest tiles first
    const int bh   = blockIdx.y;
    const int b    = bh >> 4;
    const int h    = bh & (H_ - 1);

    const size_t bhT = (size_t)bh * T_;

    // ldmatrix lane mappings (same as validated GEMM)
    const int a_row = (lane & 7) + ((lane >> 3) & 1) * 8;
    const int a_k8  = (lane >> 4) * 8;
    const int b_row = (lane & 7) + (lane >> 4) * 8;
    const int b_k8  = ((lane >> 3) & 1) * 8;

    // ---- load Q tile (128 x 128, hi/lo fp16) via cp.async ----
    {
        const __half* qh = g_qh + (bhT + qt * 128) * D_;
        const __half* ql = g_ql + (bhT + qt * 128) * D_;
        #pragma unroll
        for (int i = 0; i < 8; i++) {
            int idx = tid + i * 256;
            int row = idx >> 4, c = idx & 15;
            cp16(sb + SQ_H + row * 272 + c * 16, qh + row * D_ + c * 8);
            cp16(sb + SQ_L + row * 272 + c * 16, ql + row * D_ + c * 8);
        }
    }

    auto loadKV = [&](int blk, int buf) {
        uint32_t bo = sb + SBUF0 + buf * STG_SZ;
        const __half* kp = g_k  + (bhT + blk * 64) * D_;
        const __half* vp = g_vt + (size_t)bh * D_ * T_ + blk * 64;
        #pragma unroll
        for (int i = 0; i < 4; i++) {
            int idx = tid + i * 256;
            int row = idx >> 4, c = idx & 15;            // K: 64 rows x 16 chunks
            cp16(bo + KSTG + row * 272 + c * 16, kp + row * D_ + c * 8);
            int vr = idx >> 3, vc = idx & 7;             // V: 128 rows x 8 chunks
            cp16(bo + VSTG + vr * 144 + vc * 16, vp + (size_t)vr * T_ + vc * 8);
        }
    };

    loadKV(0, 0);
    CP_COMMIT();
    CP_WAIT0();
    __syncthreads();

    const int nblk = 2 * qt + 2;
    const float scale = 0.08838834764831845f;   // 1/sqrt(128)

    float mr0 = -INFINITY, mr1 = -INFINITY, lw0 = 0.0f, lw1 = 0.0f;
    float O[16][4];
    #pragma unroll
    for (int n = 0; n < 16; n++)
        #pragma unroll
        for (int e = 0; e < 4; e++) O[n][e] = 0.0f;

    const int rbase = qt * 128 + 16 * w;        // global row of lr==0

    for (int blk = 0; blk < nblk; blk++) {
        const uint32_t bo = sb + SBUF0 + (blk & 1) * STG_SZ;
        if (blk + 1 < nblk) {
            loadKV(blk + 1, (blk & 1) ^ 1);
            CP_COMMIT();
        }

        // ---- S = (Qh+Ql) K^T (16x64 per warp), ldmatrix fragments ----
        float s[8][4];
        #pragma unroll
        for (int n = 0; n < 8; n++)
            #pragma unroll
            for (int e = 0; e < 4; e++) s[n][e] = 0.0f;

        #pragma unroll
        for (int kt = 0; kt < 8; kt++) {
            uint32_t ah[4], al[4];
            uint32_t aq = sb + SQ_H +
                (uint32_t)((16 * w + a_row) * 272 + (kt * 16 + a_k8) * 2);
            ldsm4(ah, aq);
            ldsm4(al, aq + (SQ_L - SQ_H));
            #pragma unroll
            for (int p = 0; p < 4; p++) {
                uint32_t kf[4];
                ldsm4(kf, bo + KSTG +
                    (uint32_t)((p * 16 + b_row) * 272 + (kt * 16 + b_k8) * 2));
                mma16816h(s[2*p+0], ah, &kf[0]);
                mma16816h(s[2*p+0], al, &kf[0]);
                mma16816h(s[2*p+1], ah, &kf[2]);
                mma16816h(s[2*p+1], al, &kf[2]);
            }
        }

        // ---- scale + causal mask ----
        const bool need_mask = (blk * 64 + 63) > rbase;
        #pragma unroll
        for (int nt = 0; nt < 8; nt++) {
            #pragma unroll
            for (int e = 0; e < 4; e++) {
                float v = s[nt][e] * scale;
                if (need_mask) {
                    int ckey = blk * 64 + nt * 8 + 2 * q + (e & 1);
                    int r = rbase + lr + ((e >> 1) ? 8 : 0);
                    if (ckey > r) v = -1e30f;
                }
                s[nt][e] = v;
            }
        }

        // ---- online softmax (intra-quad shuffles) ----
        float mx0 = -1e30f, mx1 = -1e30f;
        #pragma unroll
        for (int nt = 0; nt < 8; nt++) {
            mx0 = fmaxf(mx0, fmaxf(s[nt][0], s[nt][1]));
            mx1 = fmaxf(mx1, fmaxf(s[nt][2], s[nt][3]));
        }
        mx0 = fmaxf(mx0, __shfl_xor_sync(0xffffffff, mx0, 1));
        mx0 = fmaxf(mx0, __shfl_xor_sync(0xffffffff, mx0, 2));
        mx1 = fmaxf(mx1, __shfl_xor_sync(0xffffffff, mx1, 1));
        mx1 = fmaxf(mx1, __shfl_xor_sync(0xffffffff, mx1, 2));
        float mn0 = fmaxf(mr0, mx0);
        float mn1 = fmaxf(mr1, mx1);
        float alpha0 = __expf(mr0 - mn0);
        float alpha1 = __expf(mr1 - mn1);

        float sum0 = 0.0f, sum1 = 0.0f;
        uint32_t aPh[4][4], aPl[4][4];
        #pragma unroll
        for (int nt = 0; nt < 8; nt++) {
            float p0 = __expf(s[nt][0] - mn0);
            float p1 = __expf(s[nt][1] - mn0);
            float p2 = __expf(s[nt][2] - mn1);
            float p3 = __expf(s[nt][3] - mn1);
            sum0 += p0 + p1;
            sum1 += p2 + p3;
            float h0 = __half2float(__float2half(p0));
            float h1 = __half2float(__float2half(p1));
            float h2 = __half2float(__float2half(p2));
            float h3 = __half2float(__float2half(p3));
            int kt2 = nt >> 1;
            int hi2 = (nt & 1) << 1;
            aPh[kt2][hi2 + 0] = packh(h0, h1);
            aPh[kt2][hi2 + 1] = packh(h2, h3);
            aPl[kt2][hi2 + 0] = packh(p0 - h0, p1 - h1);
            aPl[kt2][hi2 + 1] = packh(p2 - h2, p3 - h3);
        }
        sum0 += __shfl_xor_sync(0xffffffff, sum0, 1);
        sum0 += __shfl_xor_sync(0xffffffff, sum0, 2);
        sum1 += __shfl_xor_sync(0xffffffff, sum1, 1);
        sum1 += __shfl_xor_sync(0xffffffff, sum1, 2);
        lw0 = lw0 * alpha0 + sum0;
        lw1 = lw1 * alpha1 + sum1;
        mr0 = mn0;
        mr1 = mn1;

        // ---- O = O*alpha + (Ph+Pl) V, ldmatrix V fragments ----
        #pragma unroll
        for (int n = 0; n < 16; n++) {
            O[n][0] *= alpha0; O[n][1] *= alpha0;
            O[n][2] *= alpha1; O[n][3] *= alpha1;
        }
        #pragma unroll
        for (int kt2 = 0; kt2 < 4; kt2++) {
            #pragma unroll
            for (int p2 = 0; p2 < 8; p2++) {
                uint32_t vf[4];
                ldsm4(vf, bo + VSTG +
                    (uint32_t)((p2 * 16 + b_row) * 144 + (kt2 * 16 + b_k8) * 2));
                mma16816h(O[2*p2+0], aPh[kt2], &vf[0]);
                mma16816h(O[2*p2+0], aPl[kt2], &vf[0]);
                mma16816h(O[2*p2+1], aPh[kt2], &vf[2]);
                mma16816h(O[2*p2+1], aPl[kt2], &vf[2]);
            }
        }

        if (blk + 1 < nblk) {
            CP_WAIT0();
            __syncthreads();
        }
    }

    // ---- epilogue: normalize, split to fp16 hi/lo for the out-proj ----
    const float inv0 = 1.0f / lw0;
    const float inv1 = 1.0f / lw1;
    const int m0 = b * T_ + rbase + lr;
    const int m1 = m0 + 8;
    #pragma unroll
    for (int nt2 = 0; nt2 < 16; nt2++) {
        int col = h * D_ + nt2 * 8 + 2 * q;
        float o0 = O[nt2][0] * inv0, o1 = O[nt2][1] * inv0;
        float o2 = O[nt2][2] * inv1, o3 = O[nt2][3] * inv1;
        __half h0 = __float2half(o0), h1 = __float2half(o1);
        __half h2 = __float2half(o2), h3 = __float2half(o3);
        __half l0 = __float2half(o0 - __half2float(h0));
        __half l1 = __float2half(o1 - __half2float(h1));
        __half l2 = __float2half(o2 - __half2float(h2));
        __half l3 = __float2half(o3 - __half2float(h3));
        *(__half2*)(outh + (size_t)m0 * C_ + col) = __half2{h0, h1};
        *(__half2*)(outl + (size_t)m0 * C_ + col) = __half2{l0, l1};
        *(__half2*)(outh + (size_t)m1 * C_ + col) = __half2{h2, h3};
        *(__half2*)(outl + (size_t)m1 * C_ + col) = __half2{l2, l3};
    }
}

// ---------------------------------------------------------------------------
extern "C" void kernel_launch(void* const* d_in, const int* in_sizes, int n_in,
                              void* d_out, int out_size)
{
    const float* x     = (const float*)d_in[0];
    const float* W_qkv = (const float*)d_in[1];
    const float* W_out = (const float*)d_in[2];
    float* out = (float*)d_out;

    cudaFuncSetAttribute(attn_hmma,
                         cudaFuncAttributeMaxDynamicSharedMemorySize, SMEM_ATTN);
    cudaFuncSetAttribute(hmma_gemm<1>,
                         cudaFuncAttributeMaxDynamicSharedMemorySize, SMEM_GEMM);
    cudaFuncSetAttribute(hmma_gemm<0>,
                         cudaFuncAttributeMaxDynamicSharedMemorySize, SMEM_GEMM);

    __half *hA, *lA, *B1, *B2;
    cudaGetSymbolAddress((void**)&hA, g_hA);
    cudaGetSymbolAddress((void**)&lA, g_lA);
    cudaGetSymbolAddress((void**)&B1, g_B1);
    cudaGetSymbolAddress((void**)&B2, g_B2);

    const int n4 = (M_ * C_) / 4;

    // 1) split x -> fp16 hi/lo (A operand of QKV GEMM)
    split_kernel<<<(n4 + 255) / 256, 256>>>(x, hA, lA, n4);
    // 2) transpose+convert weights to single fp16
    tsplit1_kernel<<<dim3(N_QKV / 32, C_ / 32), dim3(32, 8)>>>(W_qkv, B1, N_QKV);
    tsplit1_kernel<<<dim3(C_ / 32, C_ / 32), dim3(32, 8)>>>(W_out, B2, C_);
    // 3) QKV projection + RoPE -> q fp16 hi/lo, k fp16, v fp16 transposed
    hmma_gemm<1><<<dim3(N_QKV / 128, M_ / 128), 256, SMEM_GEMM>>>(
        hA, lA, B1, nullptr, N_QKV);
    // 4) HMMA flash attention -> fp16 hi/lo (A operand of out-proj)
    attn_hmma<<<dim3(T_ / 128, B_ * H_), 256, SMEM_ATTN>>>(hA, lA);
    // 5) output projection -> d_out
    hmma_gemm<0><<<dim3(C_ / 128, M_ / 128), 256, SMEM_GEMM>>>(
        hA, lA, B2, out, C_);
}

// round 14
// speedup vs baseline: 2.1862x; 2.1572x over previous
#include <cuda_runtime.h>
#include <cuda_bf16.h>
#include <cuda_fp16.h>
#include <math.h>
#include <stdint.h>

#define B_  2
#define T_  2048
#define C_  2048
#define H_  16
#define D_  128
#define M_  (B_*T_)      // 4096
#define N_QKV (3*C_)     // 6144

// ---------------------------------------------------------------------------
// Device scratch (allocation-free per harness rules)
// ---------------------------------------------------------------------------
__device__ __half g_qv[(size_t)B_*H_*T_*D_];   // q, single fp16
__device__ __half g_k [(size_t)B_*H_*T_*D_];   // k, single fp16
__device__ __half g_vt[(size_t)B_*H_*D_*T_];   // v, single fp16, [B,H,D,T]

__device__ __half g_hA[(size_t)M_*C_];     // GEMM A operand, fp16 hi
__device__ __half g_lA[(size_t)M_*C_];     // GEMM A operand, fp16 lo (out-proj only)
__device__ __half g_B1[(size_t)N_QKV*C_];  // W_qkv^T, single fp16
__device__ __half g_B2[(size_t)C_*C_];     // W_out^T, single fp16

// ---------------------------------------------------------------------------
// PTX helpers
// ---------------------------------------------------------------------------
__device__ __forceinline__ void mma16816h(float* c, const uint32_t* a, const uint32_t* b) {
    asm volatile(
        "mma.sync.aligned.m16n8k16.row.col.f32.f16.f16.f32 "
        "{%0,%1,%2,%3}, {%4,%5,%6,%7}, {%8,%9}, {%0,%1,%2,%3};"
        : "+f"(c[0]), "+f"(c[1]), "+f"(c[2]), "+f"(c[3])
        : "r"(a[0]), "r"(a[1]), "r"(a[2]), "r"(a[3]), "r"(b[0]), "r"(b[1]));
}

__device__ __forceinline__ void ldsm4(uint32_t* r, uint32_t addr) {
    asm volatile("ldmatrix.sync.aligned.m8n8.x4.shared.b16 {%0,%1,%2,%3}, [%4];"
        : "=r"(r[0]), "=r"(r[1]), "=r"(r[2]), "=r"(r[3]) : "r"(addr));
}

__device__ __forceinline__ uint32_t smem_to_u32(const void* p) {
    uint32_t a;
    asm("{ .reg .u64 t; cvta.to.shared.u64 t, %1; cvt.u32.u64 %0, t; }" : "=r"(a) : "l"(p));
    return a;
}

__device__ __forceinline__ void cp16(uint32_t dst, const void* src) {
    asm volatile("cp.async.cg.shared.global [%0], [%1], 16;" :: "r"(dst), "l"(src));
}
#define CP_COMMIT() asm volatile("cp.async.commit_group;" ::: "memory")
#define CP_WAIT0()  asm volatile("cp.async.wait_group 0;" ::: "memory")
template<int N>
__device__ __forceinline__ void cp_wait() {
    asm volatile("cp.async.wait_group %0;" :: "n"(N) : "memory");
}

// pack two fp32 -> fp16x2 (lo = first arg -> lower half)
__device__ __forceinline__ uint32_t packh(float lo, float hi) {
    uint32_t r;
    asm("cvt.rn.f16x2.f32 %0, %1, %2;" : "=r"(r) : "f"(hi), "f"(lo));
    return r;
}

// ---------------------------------------------------------------------------
// fp32 -> fp16 single convert;  fp32 -> fp16 transpose-convert
// ---------------------------------------------------------------------------
__global__ void conv1_kernel(const float* __restrict__ src,
                             __half* __restrict__ dst, int n4)
{
    int i = blockIdx.x * blockDim.x + threadIdx.x;
    if (i >= n4) return;
    float4 v = ((const float4*)src)[i];
    __half2* dp = (__half2*)dst;
    dp[i*2]   = __half2{__float2half(v.x), __float2half(v.y)};
    dp[i*2+1] = __half2{__float2half(v.z), __float2half(v.w)};
}

// Transpose + convert: W [K=2048, N] -> fp16 [N, 2048]
__global__ void tsplit1_kernel(const float* __restrict__ W,
                               __half* __restrict__ hi, int N)
{
    __shared__ float t[32][33];
    int n0 = blockIdx.x * 32, k0 = blockIdx.y * 32;
    int tx = threadIdx.x, ty = threadIdx.y;
    #pragma unroll
    for (int i = 0; i < 4; i++)
        t[ty + i*8][tx] = W[(size_t)(k0 + ty + i*8) * N + n0 + tx];
    __syncthreads();
    #pragma unroll
    for (int i = 0; i < 4; i++) {
        int r = ty + i*8;
        hi[(size_t)(n0 + r) * 2048 + k0 + tx] = __float2half(t[tx][r]);
    }
}

// ---------------------------------------------------------------------------
// HMMA fp16 GEMM, TERMS in {1,2}: C = (Ah [+Al]) * B^T.
// cp.async pipeline (4 stages for 1-term, 3 for 2-term), ldmatrix fragments,
// CTA 128x128, 8 warps (4m x 2n), K-chunk 32, 2 CTAs/SM.
// EPI=1: RoPE; q,k -> single fp16, v -> single fp16 transposed.
// EPI=0: plain fp32 store.
// ---------------------------------------------------------------------------
#define ASTR 40                          // padded fp16 row stride
#define TILE_ELEMS (128 * ASTR)          // 5120 elems per matrix tile
#define TILE_B     (TILE_ELEMS * 2)      // 10240 bytes
#define NCH        64                    // 2048 / 32

template<int EPI, int TERMS>
__global__ void __launch_bounds__(256, 2) hmma_gemm(
    const __half* __restrict__ hiA, const __half* __restrict__ loA,
    const __half* __restrict__ Bw,
    float* __restrict__ Cout, int Ntot)
{
    constexpr int NSTAGE  = (TERMS == 1) ? 4 : 3;
    constexpr int STAGE_B = (TERMS + 1) * TILE_B;

    extern __shared__ char smraw[];
    const uint32_t sb = smem_to_u32(smraw);

    const int tid = threadIdx.x;
    const int lane = tid & 31;
    const int wid = tid >> 5;
    const int warp_m = wid & 3;
    const int warp_n = wid >> 2;
    const int bn = blockIdx.x * 128;
    const int bm = blockIdx.y * 128;

    float acc[2][8][4];
    #pragma unroll
    for (int mt = 0; mt < 2; mt++)
        #pragma unroll
        for (int nt = 0; nt < 8; nt++)
            #pragma unroll
            for (int e = 0; e < 4; e++) acc[mt][nt][e] = 0.0f;

    const int lrow = tid >> 2;
    const int lc   = (tid & 3) * 8;
    auto load_stage = [&](int st, int k0) {
        uint32_t bo = sb + st * STAGE_B;
        #pragma unroll
        for (int i = 0; i < 2; i++) {
            int row = lrow + i * 64;
            uint32_t so = (uint32_t)(row * ASTR + lc) * 2;
            size_t ga = (size_t)(bm + row) * 2048 + k0 + lc;
            size_t gb = (size_t)(bn + row) * 2048 + k0 + lc;
            cp16(bo + 0*TILE_B + so, hiA + ga);
            if (TERMS == 2)
                cp16(bo + 1*TILE_B + so, loA + ga);
            cp16(bo + (TERMS)*TILE_B + so, Bw + gb);
        }
    };

    const int a_row = warp_m * 32 + (lane & 7) + ((lane >> 3) & 1) * 8;
    const int a_k8  = (lane >> 4) * 8;
    const int b_row = warp_n * 64 + (lane & 7) + (lane >> 4) * 8;
    const int b_k8  = ((lane >> 3) & 1) * 8;

    auto compute_stage = [&](int st) {
        uint32_t bo = sb + st * STAGE_B;
        #pragma unroll
        for (int ks = 0; ks < 32; ks += 16) {
            uint32_t ah[2][4], al[2][4], bh[4][4];
            #pragma unroll
            for (int mt = 0; mt < 2; mt++) {
                uint32_t ao = (uint32_t)((a_row + mt * 16) * ASTR + ks + a_k8) * 2;
                ldsm4(ah[mt], bo + 0*TILE_B + ao);
                if (TERMS == 2)
                    ldsm4(al[mt], bo + 1*TILE_B + ao);
            }
            #pragma unroll
            for (int p = 0; p < 4; p++) {
                uint32_t bo2 = (uint32_t)((b_row + p * 16) * ASTR + ks + b_k8) * 2;
                ldsm4(bh[p], bo + (TERMS)*TILE_B + bo2);
            }
            #pragma unroll
            for (int mt = 0; mt < 2; mt++)
                #pragma unroll
                for (int p = 0; p < 4; p++) {
                    mma16816h(acc[mt][2*p+0], ah[mt], &bh[p][0]);
                    if (TERMS == 2)
                        mma16816h(acc[mt][2*p+0], al[mt], &bh[p][0]);
                    mma16816h(acc[mt][2*p+1], ah[mt], &bh[p][2]);
                    if (TERMS == 2)
                        mma16816h(acc[mt][2*p+1], al[mt], &bh[p][2]);
                }
        }
    };

    #pragma unroll
    for (int s = 0; s < NSTAGE - 1; s++) {
        load_stage(s, s * 32);
        CP_COMMIT();
    }

    for (int c = 0; c < NCH; c++) {
        cp_wait<NSTAGE - 2>();
        __syncthreads();
        compute_stage(c % NSTAGE);
        if (c + NSTAGE - 1 < NCH)
            load_stage((c + NSTAGE - 1) % NSTAGE, (c + NSTAGE - 1) * 32);
        CP_COMMIT();
    }

    // ---- Epilogue ----
    const int lr = lane >> 2;
    const int lk = (lane & 3) * 2;

    if (EPI == 1) {
        const int sub = bn >> 11;              // 0=q, 1=k, 2=v
        const int h   = (bn >> 7) & (H_ - 1);
        const float ROPE_K = 9.210340371976184f / (float)D_;
        float invf[8];
        #pragma unroll
        for (int nt = 0; nt < 8; nt++)
            invf[nt] = expf(-(float)(warp_n * 64 + nt * 8 + lk) * ROPE_K);
        #pragma unroll
        for (int mt = 0; mt < 2; mt++) {
            #pragma unroll
            for (int half = 0; half < 2; half++) {
                int m = bm + warp_m * 32 + mt * 16 + lr + half * 8;
                int bidx = m >> 11;
                int t    = m & (T_ - 1);
                size_t rowoff = ((size_t)(bidx * H_ + h) * T_ + t) * D_;
                #pragma unroll
                for (int nt = 0; nt < 8; nt++) {
                    int d = warp_n * 64 + nt * 8 + lk;
                    float v0 = acc[mt][nt][half * 2 + 0];
                    float v1 = acc[mt][nt][half * 2 + 1];
                    if (sub < 2) {
                        float sn, cs;
                        sincosf((float)t * invf[nt], &sn, &cs);
                        float o0 = v0 * cs - v1 * sn;
                        float o1 = v1 * cs + v0 * sn;
                        v0 = o0; v1 = o1;
                    }
                    if (sub == 0) {
                        *(__half2*)(g_qv + rowoff + d) =
                            __half2{__float2half(v0), __float2half(v1)};
                    } else if (sub == 1) {
                        *(__half2*)(g_k + rowoff + d) =
                            __half2{__float2half(v0), __float2half(v1)};
                    } else {
                        size_t vb = ((size_t)(bidx * H_ + h) * D_ + d) * T_ + t;
                        g_vt[vb]      = __float2half(v0);
                        g_vt[vb + T_] = __float2half(v1);
                    }
                }
            }
        }
    } else {
        #pragma unroll
        for (int mt = 0; mt < 2; mt++) {
            #pragma unroll
            for (int half = 0; half < 2; half++) {
                int m = bm + warp_m * 32 + mt * 16 + lr + half * 8;
                float* dst = Cout + (size_t)m * Ntot + bn + warp_n * 64 + lk;
                #pragma unroll
                for (int nt = 0; nt < 8; nt++)
                    *(float2*)(dst + nt * 8) =
                        make_float2(acc[mt][nt][half * 2 + 0], acc[mt][nt][half * 2 + 1]);
            }
        }
    }
}

#define SMEM_GEMM_1 (4 * 2 * TILE_B)   // 81920
#define SMEM_GEMM_2 (3 * 3 * TILE_B)   // 92160

// ---------------------------------------------------------------------------
// HMMA flash attention, single-fp16 Q/K/V/P, ldmatrix fragments.
// CTA: 128 queries, 8 warps (16 rows each). Key blocks of 64, cp.async
// double-buffered. Output -> fp16 hi/lo (out-proj A operand).
// ---------------------------------------------------------------------------
#define SQ     0
#define SBUF0  34816
#define KSTG   0
#define VSTG   17408
#define STG_SZ 35840
#define SMEM_ATTN (SBUF0 + 2 * STG_SZ)   // 106496 bytes

__global__ void __launch_bounds__(256, 1) attn_hmma(
    __half* __restrict__ outh, __half* __restrict__ outl)
{
    extern __shared__ char sm[];
    const uint32_t sb = smem_to_u32(sm);

    const int tid  = threadIdx.x;
    const int lane = tid & 31;
    const int w    = tid >> 5;
    const int lr   = lane >> 2;
    const int q    = lane & 3;
    const int qt   = 15 - blockIdx.x;          // longest tiles first
    const int bh   = blockIdx.y;
    const int b    = bh >> 4;
    const int h    = bh & (H_ - 1);

    const size_t bhT = (size_t)bh * T_;

    const int a_row = (lane & 7) + ((lane >> 3) & 1) * 8;
    const int a_k8  = (lane >> 4) * 8;
    const int b_row = (lane & 7) + (lane >> 4) * 8;
    const int b_k8  = ((lane >> 3) & 1) * 8;

    // ---- load Q tile (128 x 128 fp16) via cp.async ----
    {
        const __half* qp = g_qv + (bhT + qt * 128) * D_;
        #pragma unroll
        for (int i = 0; i < 8; i++) {
            int idx = tid + i * 256;
            int row = idx >> 4, c = idx & 15;
            cp16(sb + SQ + row * 272 + c * 16, qp + row * D_ + c * 8);
        }
    }

    auto loadKV = [&](int blk, int buf) {
        uint32_t bo = sb + SBUF0 + buf * STG_SZ;
        const __half* kp = g_k  + (bhT + blk * 64) * D_;
        const __half* vp = g_vt + (size_t)bh * D_ * T_ + blk * 64;
        #pragma unroll
        for (int i = 0; i < 4; i++) {
            int idx = tid + i * 256;
            int row = idx >> 4, c = idx & 15;            // K: 64 rows x 16 chunks
            cp16(bo + KSTG + row * 272 + c * 16, kp + row * D_ + c * 8);
            int vr = idx >> 3, vc = idx & 7;             // V: 128 rows x 8 chunks
            cp16(bo + VSTG + vr * 144 + vc * 16, vp + (size_t)vr * T_ + vc * 8);
        }
    };

    loadKV(0, 0);
    CP_COMMIT();
    CP_WAIT0();
    __syncthreads();

    const int nblk = 2 * qt + 2;
    const float scale = 0.08838834764831845f;   // 1/sqrt(128)

    float mr0 = -INFINITY, mr1 = -INFINITY, lw0 = 0.0f, lw1 = 0.0f;
    float O[16][4];
    #pragma unroll
    for (int n = 0; n < 16; n++)
        #pragma unroll
        for (int e = 0; e < 4; e++) O[n][e] = 0.0f;

    const int rbase = qt * 128 + 16 * w;        // global row of lr==0

    for (int blk = 0; blk < nblk; blk++) {
        const uint32_t bo = sb + SBUF0 + (blk & 1) * STG_SZ;
        if (blk + 1 < nblk) {
            loadKV(blk + 1, (blk & 1) ^ 1);
            CP_COMMIT();
        }

        // ---- S = Q K^T (16x64 per warp), ldmatrix fragments ----
        float s[8][4];
        #pragma unroll
        for (int n = 0; n < 8; n++)
            #pragma unroll
            for (int e = 0; e < 4; e++) s[n][e] = 0.0f;

        #pragma unroll
        for (int kt = 0; kt < 8; kt++) {
            uint32_t ah[4];
            ldsm4(ah, sb + SQ +
                (uint32_t)((16 * w + a_row) * 272 + (kt * 16 + a_k8) * 2));
            #pragma unroll
            for (int p = 0; p < 4; p++) {
                uint32_t kf[4];
                ldsm4(kf, bo + KSTG +
                    (uint32_t)((p * 16 + b_row) * 272 + (kt * 16 + b_k8) * 2));
                mma16816h(s[2*p+0], ah, &kf[0]);
                mma16816h(s[2*p+1], ah, &kf[2]);
            }
        }

        // ---- scale + causal mask ----
        const bool need_mask = (blk * 64 + 63) > rbase;
        #pragma unroll
        for (int nt = 0; nt < 8; nt++) {
            #pragma unroll
            for (int e = 0; e < 4; e++) {
                float v = s[nt][e] * scale;
                if (need_mask) {
                    int ckey = blk * 64 + nt * 8 + 2 * q + (e & 1);
                    int r = rbase + lr + ((e >> 1) ? 8 : 0);
                    if (ckey > r) v = -1e30f;
                }
                s[nt][e] = v;
            }
        }

        // ---- online softmax (intra-quad shuffles) ----
        float mx0 = -1e30f, mx1 = -1e30f;
        #pragma unroll
        for (int nt = 0; nt < 8; nt++) {
            mx0 = fmaxf(mx0, fmaxf(s[nt][0], s[nt][1]));
            mx1 = fmaxf(mx1, fmaxf(s[nt][2], s[nt][3]));
        }
        mx0 = fmaxf(mx0, __shfl_xor_sync(0xffffffff, mx0, 1));
        mx0 = fmaxf(mx0, __shfl_xor_sync(0xffffffff, mx0, 2));
        mx1 = fmaxf(mx1, __shfl_xor_sync(0xffffffff, mx1, 1));
        mx1 = fmaxf(mx1, __shfl_xor_sync(0xffffffff, mx1, 2));
        float mn0 = fmaxf(mr0, mx0);
        float mn1 = fmaxf(mr1, mx1);
        float alpha0 = __expf(mr0 - mn0);
        float alpha1 = __expf(mr1 - mn1);

        float sum0 = 0.0f, sum1 = 0.0f;
        uint32_t aPh[4][4];
        #pragma unroll
        for (int nt = 0; nt < 8; nt++) {
            float p0 = __expf(s[nt][0] - mn0);
            float p1 = __expf(s[nt][1] - mn0);
            float p2 = __expf(s[nt][2] - mn1);
            float p3 = __expf(s[nt][3] - mn1);
            sum0 += p0 + p1;
            sum1 += p2 + p3;
            int kt2 = nt >> 1;
            int hi2 = (nt & 1) << 1;
            aPh[kt2][hi2 + 0] = packh(p0, p1);
            aPh[kt2][hi2 + 1] = packh(p2, p3);
        }
        sum0 += __shfl_xor_sync(0xffffffff, sum0, 1);
        sum0 += __shfl_xor_sync(0xffffffff, sum0, 2);
        sum1 += __shfl_xor_sync(0xffffffff, sum1, 1);
        sum1 += __shfl_xor_sync(0xffffffff, sum1, 2);
        lw0 = lw0 * alpha0 + sum0;
        lw1 = lw1 * alpha1 + sum1;
        mr0 = mn0;
        mr1 = mn1;

        // ---- O = O*alpha + P V, ldmatrix V fragments ----
        #pragma unroll
        for (int n = 0; n < 16; n++) {
            O[n][0] *= alpha0; O[n][1] *= alpha0;
            O[n][2] *= alpha1; O[n][3] *= alpha1;
        }
        #pragma unroll
        for (int kt2 = 0; kt2 < 4; kt2++) {
            #pragma unroll
            for (int p2 = 0; p2 < 8; p2++) {
                uint32_t vf[4];
                ldsm4(vf, bo + VSTG +
                    (uint32_t)((p2 * 16 + b_row) * 144 + (kt2 * 16 + b_k8) * 2));
                mma16816h(O[2*p2+0], aPh[kt2], &vf[0]);
                mma16816h(O[2*p2+1], aPh[kt2], &vf[2]);
            }
        }

        if (blk + 1 < nblk) {
            CP_WAIT0();
            __syncthreads();
        }
    }

    // ---- epilogue: normalize, split to fp16 hi/lo for the 2-term out-proj ----
    const float inv0 = 1.0f / lw0;
    const float inv1 = 1.0f / lw1;
    const int m0 = b * T_ + rbase + lr;
    const int m1 = m0 + 8;
    #pragma unroll
    for (int nt2 = 0; nt2 < 16; nt2++) {
        int col = h * D_ + nt2 * 8 + 2 * q;
        float o0 = O[nt2][0] * inv0, o1 = O[nt2][1] * inv0;
        float o2 = O[nt2][2] * inv1, o3 = O[nt2][3] * inv1;
        __half h0 = __float2half(o0), h1 = __float2half(o1);
        __half h2 = __float2half(o2), h3 = __float2half(o3);
        __half l0 = __float2half(o0 - __half2float(h0));
        __half l1 = __float2half(o1 - __half2float(h1));
        __half l2 = __float2half(o2 - __half2float(h2));
        __half l3 = __float2half(o3 - __half2float(h3));
        *(__half2*)(outh + (size_t)m0 * C_ + col) = __half2{h0, h1};
        *(__half2*)(outl + (size_t)m0 * C_ + col) = __half2{l0, l1};
        *(__half2*)(outh + (size_t)m1 * C_ + col) = __half2{h2, h3};
        *(__half2*)(outl + (size_t)m1 * C_ + col) = __half2{l2, l3};
    }
}

// ---------------------------------------------------------------------------
extern "C" void kernel_launch(void* const* d_in, const int* in_sizes, int n_in,
                              void* d_out, int out_size)
{
    const float* x     = (const float*)d_in[0];
    const float* W_qkv = (const float*)d_in[1];
    const float* W_out = (const float*)d_in[2];
    float* out = (float*)d_out;

    cudaFuncSetAttribute(attn_hmma,
                         cudaFuncAttributeMaxDynamicSharedMemorySize, SMEM_ATTN);
    cudaFuncSetAttribute(hmma_gemm<1, 1>,
                         cudaFuncAttributeMaxDynamicSharedMemorySize, SMEM_GEMM_1);
    cudaFuncSetAttribute(hmma_gemm<0, 2>,
                         cudaFuncAttributeMaxDynamicSharedMemorySize, SMEM_GEMM_2);

    __half *hA, *lA, *B1, *B2;
    cudaGetSymbolAddress((void**)&hA, g_hA);
    cudaGetSymbolAddress((void**)&lA, g_lA);
    cudaGetSymbolAddress((void**)&B1, g_B1);
    cudaGetSymbolAddress((void**)&B2, g_B2);

    const int n4 = (M_ * C_) / 4;

    // 1) convert x -> single fp16 (A operand of QKV GEMM)
    conv1_kernel<<<(n4 + 255) / 256, 256>>>(x, hA, n4);
    // 2) transpose+convert weights to single fp16
    tsplit1_kernel<<<dim3(N_QKV / 32, C_ / 32), dim3(32, 8)>>>(W_qkv, B1, N_QKV);
    tsplit1_kernel<<<dim3(C_ / 32, C_ / 32), dim3(32, 8)>>>(W_out, B2, C_);
    // 3) QKV projection (1-term) + RoPE -> q,k fp16, v fp16 transposed
    hmma_gemm<1, 1><<<dim3(N_QKV / 128, M_ / 128), 256, SMEM_GEMM_1>>>(
        hA, nullptr, B1, nullptr, N_QKV);
    // 4) HMMA flash attention (single-fp16) -> fp16 hi/lo (out-proj A operand)
    attn_hmma<<<dim3(T_ / 128, B_ * H_), 256, SMEM_ATTN>>>(hA, lA);
    // 5) output projection (2-term) -> d_out
    hmma_gemm<0, 2><<<dim3(C_ / 128, M_ / 128), 256, SMEM_GEMM_2>>>(
        hA, lA, B2, out, C_);
}

// round 17
// speedup vs baseline: 2.4685x; 1.1292x over previous
#include <cuda_runtime.h>
#include <cuda_bf16.h>
#include <cuda_fp16.h>
#include <math.h>
#include <stdint.h>

#define B_  2
#define T_  2048
#define C_  2048
#define H_  16
#define D_  128
#define M_  (B_*T_)      // 4096
#define N_QKV (3*C_)     // 6144

// ---------------------------------------------------------------------------
// Device scratch (allocation-free per harness rules)
// ---------------------------------------------------------------------------
__device__ __half g_qv[(size_t)B_*H_*T_*D_];   // q, single fp16
__device__ __half g_k [(size_t)B_*H_*T_*D_];   // k, single fp16
__device__ __half g_vt[(size_t)B_*H_*D_*T_];   // v, single fp16, [B,H,D,T]

__device__ __half g_hA[(size_t)M_*C_];     // GEMM A operand, single fp16
__device__ __half g_B1[(size_t)N_QKV*C_];  // W_qkv^T, single fp16
__device__ __half g_B2[(size_t)C_*C_];     // W_out^T, single fp16

// ---------------------------------------------------------------------------
// PTX helpers
// ---------------------------------------------------------------------------
__device__ __forceinline__ void mma16816h(float* c, const uint32_t* a, const uint32_t* b) {
    asm volatile(
        "mma.sync.aligned.m16n8k16.row.col.f32.f16.f16.f32 "
        "{%0,%1,%2,%3}, {%4,%5,%6,%7}, {%8,%9}, {%0,%1,%2,%3};"
        : "+f"(c[0]), "+f"(c[1]), "+f"(c[2]), "+f"(c[3])
        : "r"(a[0]), "r"(a[1]), "r"(a[2]), "r"(a[3]), "r"(b[0]), "r"(b[1]));
}

__device__ __forceinline__ void ldsm4(uint32_t* r, uint32_t addr) {
    asm volatile("ldmatrix.sync.aligned.m8n8.x4.shared.b16 {%0,%1,%2,%3}, [%4];"
        : "=r"(r[0]), "=r"(r[1]), "=r"(r[2]), "=r"(r[3]) : "r"(addr));
}

__device__ __forceinline__ uint32_t smem_to_u32(const void* p) {
    uint32_t a;
    asm("{ .reg .u64 t; cvta.to.shared.u64 t, %1; cvt.u32.u64 %0, t; }" : "=r"(a) : "l"(p));
    return a;
}

__device__ __forceinline__ void cp16(uint32_t dst, const void* src) {
    asm volatile("cp.async.cg.shared.global [%0], [%1], 16;" :: "r"(dst), "l"(src));
}
#define CP_COMMIT() asm volatile("cp.async.commit_group;" ::: "memory")
#define CP_WAIT0()  asm volatile("cp.async.wait_group 0;" ::: "memory")
template<int N>
__device__ __forceinline__ void cp_wait() {
    asm volatile("cp.async.wait_group %0;" :: "n"(N) : "memory");
}

// pack two fp32 -> fp16x2 (lo = first arg -> lower half)
__device__ __forceinline__ uint32_t packh(float lo, float hi) {
    uint32_t r;
    asm("cvt.rn.f16x2.f32 %0, %1, %2;" : "=r"(r) : "f"(hi), "f"(lo));
    return r;
}

// ---------------------------------------------------------------------------
// fp32 -> fp16 single convert;  fp32 -> fp16 transpose-convert
// ---------------------------------------------------------------------------
__global__ void conv1_kernel(const float* __restrict__ src,
                             __half* __restrict__ dst, int n4)
{
    int i = blockIdx.x * blockDim.x + threadIdx.x;
    if (i >= n4) return;
    float4 v = ((const float4*)src)[i];
    __half2* dp = (__half2*)dst;
    dp[i*2]   = __half2{__float2half(v.x), __float2half(v.y)};
    dp[i*2+1] = __half2{__float2half(v.z), __float2half(v.w)};
}

// Transpose + convert: W [K=2048, N] -> fp16 [N, 2048]
__global__ void tsplit1_kernel(const float* __restrict__ W,
                               __half* __restrict__ hi, int N)
{
    __shared__ float t[32][33];
    int n0 = blockIdx.x * 32, k0 = blockIdx.y * 32;
    int tx = threadIdx.x, ty = threadIdx.y;
    #pragma unroll
    for (int i = 0; i < 4; i++)
        t[ty + i*8][tx] = W[(size_t)(k0 + ty + i*8) * N + n0 + tx];
    __syncthreads();
    #pragma unroll
    for (int i = 0; i < 4; i++) {
        int r = ty + i*8;
        hi[(size_t)(n0 + r) * 2048 + k0 + tx] = __float2half(t[tx][r]);
    }
}

// ---------------------------------------------------------------------------
// HMMA fp16 1-term GEMM: C = A * B^T.  cp.async 4-stage pipeline, ldmatrix
// fragments, CTA 128x128, 8 warps (4m x 2n), K-chunk 32, 2 CTAs/SM.
// EPI=1: RoPE; q,k -> single fp16, v -> single fp16 transposed.
// EPI=0: plain fp32 store.
// ---------------------------------------------------------------------------
#define ASTR 40                          // padded fp16 row stride
#define TILE_ELEMS (128 * ASTR)          // 5120 elems per matrix tile
#define TILE_B     (TILE_ELEMS * 2)      // 10240 bytes
#define NSTAGE     4
#define STAGE_B    (2 * TILE_B)          // A + B tiles
#define SMEM_GEMM  (NSTAGE * STAGE_B)    // 81920 bytes -> 2 CTAs/SM
#define NCH        64                    // 2048 / 32

template<int EPI>
__global__ void __launch_bounds__(256, 2) hmma_gemm(
    const __half* __restrict__ Aw, const __half* __restrict__ Bw,
    float* __restrict__ Cout, int Ntot)
{
    extern __shared__ char smraw[];
    const uint32_t sb = smem_to_u32(smraw);

    const int tid = threadIdx.x;
    const int lane = tid & 31;
    const int wid = tid >> 5;
    const int warp_m = wid & 3;
    const int warp_n = wid >> 2;
    const int bn = blockIdx.x * 128;
    const int bm = blockIdx.y * 128;

    float acc[2][8][4];
    #pragma unroll
    for (int mt = 0; mt < 2; mt++)
        #pragma unroll
        for (int nt = 0; nt < 8; nt++)
            #pragma unroll
            for (int e = 0; e < 4; e++) acc[mt][nt][e] = 0.0f;

    const int lrow = tid >> 2;
    const int lc   = (tid & 3) * 8;
    auto load_stage = [&](int st, int k0) {
        uint32_t bo = sb + st * STAGE_B;
        #pragma unroll
        for (int i = 0; i < 2; i++) {
            int row = lrow + i * 64;
            uint32_t so = (uint32_t)(row * ASTR + lc) * 2;
            cp16(bo + 0*TILE_B + so, Aw + (size_t)(bm + row) * 2048 + k0 + lc);
            cp16(bo + 1*TILE_B + so, Bw + (size_t)(bn + row) * 2048 + k0 + lc);
        }
    };

    const int a_row = warp_m * 32 + (lane & 7) + ((lane >> 3) & 1) * 8;
    const int a_k8  = (lane >> 4) * 8;
    const int b_row = warp_n * 64 + (lane & 7) + (lane >> 4) * 8;
    const int b_k8  = ((lane >> 3) & 1) * 8;

    auto compute_stage = [&](int st) {
        uint32_t bo = sb + st * STAGE_B;
        #pragma unroll
        for (int ks = 0; ks < 32; ks += 16) {
            uint32_t ah[2][4], bh[4][4];
            #pragma unroll
            for (int mt = 0; mt < 2; mt++) {
                uint32_t ao = (uint32_t)((a_row + mt * 16) * ASTR + ks + a_k8) * 2;
                ldsm4(ah[mt], bo + 0*TILE_B + ao);
            }
            #pragma unroll
            for (int p = 0; p < 4; p++) {
                uint32_t bo2 = (uint32_t)((b_row + p * 16) * ASTR + ks + b_k8) * 2;
                ldsm4(bh[p], bo + 1*TILE_B + bo2);
            }
            #pragma unroll
            for (int mt = 0; mt < 2; mt++)
                #pragma unroll
                for (int p = 0; p < 4; p++) {
                    mma16816h(acc[mt][2*p+0], ah[mt], &bh[p][0]);
                    mma16816h(acc[mt][2*p+1], ah[mt], &bh[p][2]);
                }
        }
    };

    #pragma unroll
    for (int s = 0; s < NSTAGE - 1; s++) {
        load_stage(s, s * 32);
        CP_COMMIT();
    }

    for (int c = 0; c < NCH; c++) {
        cp_wait<NSTAGE - 2>();
        __syncthreads();
        compute_stage(c % NSTAGE);
        if (c + NSTAGE - 1 < NCH)
            load_stage((c + NSTAGE - 1) % NSTAGE, (c + NSTAGE - 1) * 32);
        CP_COMMIT();
    }

    // ---- Epilogue ----
    const int lr = lane >> 2;
    const int lk = (lane & 3) * 2;

    if (EPI == 1) {
        const int sub = bn >> 11;              // 0=q, 1=k, 2=v
        const int h   = (bn >> 7) & (H_ - 1);
        const float ROPE_K = 9.210340371976184f / (float)D_;
        float invf[8];
        #pragma unroll
        for (int nt = 0; nt < 8; nt++)
            invf[nt] = expf(-(float)(warp_n * 64 + nt * 8 + lk) * ROPE_K);
        #pragma unroll
        for (int mt = 0; mt < 2; mt++) {
            #pragma unroll
            for (int half = 0; half < 2; half++) {
                int m = bm + warp_m * 32 + mt * 16 + lr + half * 8;
                int bidx = m >> 11;
                int t    = m & (T_ - 1);
                size_t rowoff = ((size_t)(bidx * H_ + h) * T_ + t) * D_;
                #pragma unroll
                for (int nt = 0; nt < 8; nt++) {
                    int d = warp_n * 64 + nt * 8 + lk;
                    float v0 = acc[mt][nt][half * 2 + 0];
                    float v1 = acc[mt][nt][half * 2 + 1];
                    if (sub < 2) {
                        float sn, cs;
                        sincosf((float)t * invf[nt], &sn, &cs);
                        float o0 = v0 * cs - v1 * sn;
                        float o1 = v1 * cs + v0 * sn;
                        v0 = o0; v1 = o1;
                    }
                    if (sub == 0) {
                        *(__half2*)(g_qv + rowoff + d) =
                            __half2{__float2half(v0), __float2half(v1)};
                    } else if (sub == 1) {
                        *(__half2*)(g_k + rowoff + d) =
                            __half2{__float2half(v0), __float2half(v1)};
                    } else {
                        size_t vb = ((size_t)(bidx * H_ + h) * D_ + d) * T_ + t;
                        g_vt[vb]      = __float2half(v0);
                        g_vt[vb + T_] = __float2half(v1);
                    }
                }
            }
        }
    } else {
        #pragma unroll
        for (int mt = 0; mt < 2; mt++) {
            #pragma unroll
            for (int half = 0; half < 2; half++) {
                int m = bm + warp_m * 32 + mt * 16 + lr + half * 8;
                float* dst = Cout + (size_t)m * Ntot + bn + warp_n * 64 + lk;
                #pragma unroll
                for (int nt = 0; nt < 8; nt++)
                    *(float2*)(dst + nt * 8) =
                        make_float2(acc[mt][nt][half * 2 + 0], acc[mt][nt][half * 2 + 1]);
            }
        }
    }
}

// ---------------------------------------------------------------------------
// HMMA flash attention, single-fp16 Q/K/V/P, ldmatrix fragments.
// CTA: 128 queries, 8 warps (16 rows each). Key blocks of 64, cp.async
// double-buffered. Output -> single fp16 (out-proj A operand).
// ---------------------------------------------------------------------------
#define SQ     0
#define SBUF0  34816
#define KSTG   0
#define VSTG   17408
#define STG_SZ 35840
#define SMEM_ATTN (SBUF0 + 2 * STG_SZ)   // 106496 bytes

__global__ void __launch_bounds__(256, 1) attn_hmma(__half* __restrict__ outh)
{
    extern __shared__ char sm[];
    const uint32_t sb = smem_to_u32(sm);

    const int tid  = threadIdx.x;
    const int lane = tid & 31;
    const int w    = tid >> 5;
    const int lr   = lane >> 2;
    const int q    = lane & 3;
    const int qt   = 15 - blockIdx.x;          // longest tiles first
    const int bh   = blockIdx.y;
    const int b    = bh >> 4;
    const int h    = bh & (H_ - 1);

    const size_t bhT = (size_t)bh * T_;

    const int a_row = (lane & 7) + ((lane >> 3) & 1) * 8;
    const int a_k8  = (lane >> 4) * 8;
    const int b_row = (lane & 7) + (lane >> 4) * 8;
    const int b_k8  = ((lane >> 3) & 1) * 8;

    // ---- load Q tile (128 x 128 fp16) via cp.async ----
    {
        const __half* qp = g_qv + (bhT + qt * 128) * D_;
        #pragma unroll
        for (int i = 0; i < 8; i++) {
            int idx = tid + i * 256;
            int row = idx >> 4, c = idx & 15;
            cp16(sb + SQ + row * 272 + c * 16, qp + row * D_ + c * 8);
        }
    }

    auto loadKV = [&](int blk, int buf) {
        uint32_t bo = sb + SBUF0 + buf * STG_SZ;
        const __half* kp = g_k  + (bhT + blk * 64) * D_;
        const __half* vp = g_vt + (size_t)bh * D_ * T_ + blk * 64;
        #pragma unroll
        for (int i = 0; i < 4; i++) {
            int idx = tid + i * 256;
            int row = idx >> 4, c = idx & 15;            // K: 64 rows x 16 chunks
            cp16(bo + KSTG + row * 272 + c * 16, kp + row * D_ + c * 8);
            int vr = idx >> 3, vc = idx & 7;             // V: 128 rows x 8 chunks
            cp16(bo + VSTG + vr * 144 + vc * 16, vp + (size_t)vr * T_ + vc * 8);
        }
    };

    loadKV(0, 0);
    CP_COMMIT();
    CP_WAIT0();
    __syncthreads();

    const int nblk = 2 * qt + 2;
    const float scale = 0.08838834764831845f;   // 1/sqrt(128)

    float mr0 = -INFINITY, mr1 = -INFINITY, lw0 = 0.0f, lw1 = 0.0f;
    float O[16][4];
    #pragma unroll
    for (int n = 0; n < 16; n++)
        #pragma unroll
        for (int e = 0; e < 4; e++) O[n][e] = 0.0f;

    const int rbase = qt * 128 + 16 * w;        // global row of lr==0

    for (int blk = 0; blk < nblk; blk++) {
        const uint32_t bo = sb + SBUF0 + (blk & 1) * STG_SZ;
        if (blk + 1 < nblk) {
            loadKV(blk + 1, (blk & 1) ^ 1);
            CP_COMMIT();
        }

        // ---- S = Q K^T (16x64 per warp), ldmatrix fragments ----
        float s[8][4];
        #pragma unroll
        for (int n = 0; n < 8; n++)
            #pragma unroll
            for (int e = 0; e < 4; e++) s[n][e] = 0.0f;

        #pragma unroll
        for (int kt = 0; kt < 8; kt++) {
            uint32_t ah[4];
            ldsm4(ah, sb + SQ +
                (uint32_t)((16 * w + a_row) * 272 + (kt * 16 + a_k8) * 2));
            #pragma unroll
            for (int p = 0; p < 4; p++) {
                uint32_t kf[4];
                ldsm4(kf, bo + KSTG +
                    (uint32_t)((p * 16 + b_row) * 272 + (kt * 16 + b_k8) * 2));
                mma16816h(s[2*p+0], ah, &kf[0]);
                mma16816h(s[2*p+1], ah, &kf[2]);
            }
        }

        // ---- scale + causal mask ----
        const bool need_mask = (blk * 64 + 63) > rbase;
        #pragma unroll
        for (int nt = 0; nt < 8; nt++) {
            #pragma unroll
            for (int e = 0; e < 4; e++) {
                float v = s[nt][e] * scale;
                if (need_mask) {
                    int ckey = blk * 64 + nt * 8 + 2 * q + (e & 1);
                    int r = rbase + lr + ((e >> 1) ? 8 : 0);
                    if (ckey > r) v = -1e30f;
                }
                s[nt][e] = v;
            }
        }

        // ---- online softmax (intra-quad shuffles) ----
        float mx0 = -1e30f, mx1 = -1e30f;
        #pragma unroll
        for (int nt = 0; nt < 8; nt++) {
            mx0 = fmaxf(mx0, fmaxf(s[nt][0], s[nt][1]));
            mx1 = fmaxf(mx1, fmaxf(s[nt][2], s[nt][3]));
        }
        mx0 = fmaxf(mx0, __shfl_xor_sync(0xffffffff, mx0, 1));
        mx0 = fmaxf(mx0, __shfl_xor_sync(0xffffffff, mx0, 2));
        mx1 = fmaxf(mx1, __shfl_xor_sync(0xffffffff, mx1, 1));
        mx1 = fmaxf(mx1, __shfl_xor_sync(0xffffffff, mx1, 2));
        float mn0 = fmaxf(mr0, mx0);
        float mn1 = fmaxf(mr1, mx1);
        float alpha0 = __expf(mr0 - mn0);
        float alpha1 = __expf(mr1 - mn1);

        float sum0 = 0.0f, sum1 = 0.0f;
        uint32_t aPh[4][4];
        #pragma unroll
        for (int nt = 0; nt < 8; nt++) {
            float p0 = __expf(s[nt][0] - mn0);
            float p1 = __expf(s[nt][1] - mn0);
            float p2 = __expf(s[nt][2] - mn1);
            float p3 = __expf(s[nt][3] - mn1);
            sum0 += p0 + p1;
            sum1 += p2 + p3;
            int kt2 = nt >> 1;
            int hi2 = (nt & 1) << 1;
            aPh[kt2][hi2 + 0] = packh(p0, p1);
            aPh[kt2][hi2 + 1] = packh(p2, p3);
        }
        sum0 += __shfl_xor_sync(0xffffffff, sum0, 1);
        sum0 += __shfl_xor_sync(0xffffffff, sum0, 2);
        sum1 += __shfl_xor_sync(0xffffffff, sum1, 1);
        sum1 += __shfl_xor_sync(0xffffffff, sum1, 2);
        lw0 = lw0 * alpha0 + sum0;
        lw1 = lw1 * alpha1 + sum1;
        mr0 = mn0;
        mr1 = mn1;

        // ---- O = O*alpha + P V, ldmatrix V fragments ----
        #pragma unroll
        for (int n = 0; n < 16; n++) {
            O[n][0] *= alpha0; O[n][1] *= alpha0;
            O[n][2] *= alpha1; O[n][3] *= alpha1;
        }
        #pragma unroll
        for (int kt2 = 0; kt2 < 4; kt2++) {
            #pragma unroll
            for (int p2 = 0; p2 < 8; p2++) {
                uint32_t vf[4];
                ldsm4(vf, bo + VSTG +
                    (uint32_t)((p2 * 16 + b_row) * 144 + (kt2 * 16 + b_k8) * 2));
                mma16816h(O[2*p2+0], aPh[kt2], &vf[0]);
                mma16816h(O[2*p2+1], aPh[kt2], &vf[2]);
            }
        }

        if (blk + 1 < nblk) {
            CP_WAIT0();
            __syncthreads();
        }
    }

    // ---- epilogue: normalize, single-fp16 store for the 1-term out-proj ----
    const float inv0 = 1.0f / lw0;
    const float inv1 = 1.0f / lw1;
    const int m0 = b * T_ + rbase + lr;
    const int m1 = m0 + 8;
    #pragma unroll
    for (int nt2 = 0; nt2 < 16; nt2++) {
        int col = h * D_ + nt2 * 8 + 2 * q;
        *(__half2*)(outh + (size_t)m0 * C_ + col) =
            __half2{__float2half(O[nt2][0] * inv0), __float2half(O[nt2][1] * inv0)};
        *(__half2*)(outh + (size_t)m1 * C_ + col) =
            __half2{__float2half(O[nt2][2] * inv1), __float2half(O[nt2][3] * inv1)};
    }
}

// ---------------------------------------------------------------------------
extern "C" void kernel_launch(void* const* d_in, const int* in_sizes, int n_in,
                              void* d_out, int out_size)
{
    const float* x     = (const float*)d_in[0];
    const float* W_qkv = (const float*)d_in[1];
    const float* W_out = (const float*)d_in[2];
    float* out = (float*)d_out;

    cudaFuncSetAttribute(attn_hmma,
                         cudaFuncAttributeMaxDynamicSharedMemorySize, SMEM_ATTN);
    cudaFuncSetAttribute(hmma_gemm<1>,
                         cudaFuncAttributeMaxDynamicSharedMemorySize, SMEM_GEMM);
    cudaFuncSetAttribute(hmma_gemm<0>,
                         cudaFuncAttributeMaxDynamicSharedMemorySize, SMEM_GEMM);

    __half *hA, *B1, *B2;
    cudaGetSymbolAddress((void**)&hA, g_hA);
    cudaGetSymbolAddress((void**)&B1, g_B1);
    cudaGetSymbolAddress((void**)&B2, g_B2);

    const int n4 = (M_ * C_) / 4;

    // 1) convert x -> single fp16 (A operand of QKV GEMM)
    conv1_kernel<<<(n4 + 255) / 256, 256>>>(x, hA, n4);
    // 2) transpose+convert weights to single fp16
    tsplit1_kernel<<<dim3(N_QKV / 32, C_ / 32), dim3(32, 8)>>>(W_qkv, B1, N_QKV);
    tsplit1_kernel<<<dim3(C_ / 32, C_ / 32), dim3(32, 8)>>>(W_out, B2, C_);
    // 3) QKV projection (1-term) + RoPE -> q,k fp16, v fp16 transposed
    hmma_gemm<1><<<dim3(N_QKV / 128, M_ / 128), 256, SMEM_GEMM>>>(
        hA, B1, nullptr, N_QKV);
    // 4) HMMA flash attention -> single fp16 (out-proj A operand)
    attn_hmma<<<dim3(T_ / 128, B_ * H_), 256, SMEM_ATTN>>>(hA);
    // 5) output projection (1-term) -> d_out
    hmma_gemm<0><<<dim3(C_ / 128, M_ / 128), 256, SMEM_GEMM>>>(
        hA, B2, out, C_);
}